// round 3
// baseline (speedup 1.0000x reference)
#include <cuda_runtime.h>

// Operator3D: bs=4, v=8192, n=20, SUPPORT=4, KERNEL=32  (S*K = 128)
// inputs: [0] neighbor_index int32 (bs,v,n)
//         [1] vertices       f32   (bs,v,3)
//         [2] weights        f32   (1,1,4,32)
//         [3] displacement   f32   (3,128)
// output: feature f32 (bs,v,32)
//
// Strategy: one warp processes TWO rows at a time, packed into f32x2 lanes
// (component 0 = rowA, component 1 = rowB). Persistent warps stride over
// row-pairs with a 2-deep software pipeline: idx prefetched 2 chunks ahead,
// gathered vertices 1 chunk ahead, so the dependent gather chain hides
// behind the ~460-instruction compute loop.

#define BS_    4
#define V_     8192
#define N_     20
#define K_     32
#define SK_    128
#define ROWS_  (BS_ * V_)
#define NPAIRS (ROWS_ / 2)          // 16384

#define WPB      8
#define THREADS_ (WPB * 32)
#define BLOCKS_  444                 // 3 * 148: exactly 3 blocks/SM, one wave
#define NWARPS_  (BLOCKS_ * WPB)     // 3552

typedef unsigned long long u64;

__device__ __forceinline__ u64 packf2(float lo, float hi) {
    u64 r;
    asm("mov.b64 %0, {%1, %2};" : "=l"(r) : "f"(lo), "f"(hi));
    return r;
}
__device__ __forceinline__ void unpackf2(float& lo, float& hi, u64 v) {
    asm("mov.b64 {%0, %1}, %2;" : "=f"(lo), "=f"(hi) : "l"(v));
}
#define FMA_F32X2(out, a, b, c) \
    asm("fma.rn.f32x2 %0, %1, %2, %3;" : "=l"(out) : "l"(a), "l"(b), "l"(c))
#define MUL_F32X2_(out, a, b) \
    asm("mul.rn.f32x2 %0, %1, %2;" : "=l"(out) : "l"(a), "l"(b))

// smem: per neighbor j, rowA/rowB displacement pairs, f32x2-ready
struct PairDisp {
    float x[2];   // (dxA, dxB)
    float y[2];
    float z[2];
};                // 24 bytes; offsets 0/8/16 are 8B aligned (stride 24)

__global__ __launch_bounds__(THREADS_)
void op3d_kernel(const int*   __restrict__ nb,
                 const float* __restrict__ verts,
                 const float* __restrict__ weights,
                 const float* __restrict__ disp,
                 float*       __restrict__ out)
{
    __shared__ PairDisp sd[WPB][N_];

    const int warp = threadIdx.x >> 5;
    const int lane = threadIdx.x & 31;
    const int gw   = blockIdx.x * WPB + warp;
    const bool g   = (lane < N_);          // gather lane: handles neighbor j=lane of BOTH rows

    // Duplicated displacement-matrix columns: D[d][s] broadcast into both f32x2 lanes
    u64 D0[4], D1[4], D2[4];
    #pragma unroll
    for (int s = 0; s < 4; s++) {
        float a0 = disp[0*SK_ + s*32 + lane];
        float a1 = disp[1*SK_ + s*32 + lane];
        float a2 = disp[2*SK_ + s*32 + lane];
        D0[s] = packf2(a0, a0);
        D1[s] = packf2(a1, a1);
        D2[s] = packf2(a2, a2);
    }
    const float w0 = weights[ 0 + lane];
    const float w1 = weights[32 + lane];
    const float w2 = weights[64 + lane];
    const float w3 = weights[96 + lane];

    // ---- pipeline state ----
    int   p = gw;                            // current pair (gw < NWARPS_ <= NPAIRS)
    float pax=0,pay=0,paz=0, pbx=0,pby=0,pbz=0;   // gathered neighbor verts (current)
    float qax=0,qay=0,qaz=0, qbx=0,qby=0,qbz=0;   // center verts (current)
    int   nidxA=0, nidxB=0;                  // neighbor indices for NEXT pair

    // prologue: fully load current pair's gather data (one exposed stall, once)
    {
        const int rA = 2*p, rB = 2*p + 1;
        const int vb = (p >> 12) * (V_ * 3);     // batch base (p>>12 == rA>>13)
        if (g) {
            int ia = nb[rA * N_ + lane];
            int ib = nb[rB * N_ + lane];
            const float* pa = verts + vb + ia * 3;
            const float* pb = verts + vb + ib * 3;
            pax = pa[0]; pay = pa[1]; paz = pa[2];
            pbx = pb[0]; pby = pb[1]; pbz = pb[2];
            const float* qa = verts + rA * 3;
            const float* qb = verts + rB * 3;
            qax = qa[0]; qay = qa[1]; qaz = qa[2];
            qbx = qb[0]; qby = qb[1]; qbz = qb[2];
        }
        int pn = p + NWARPS_;
        if (g && pn < NPAIRS) {
            nidxA = nb[(2*pn)     * N_ + lane];
            nidxB = nb[(2*pn + 1) * N_ + lane];
        }
    }

    for (;;) {
        const int rA = 2*p, rB = 2*p + 1;
        const int pn = p + NWARPS_;
        const bool more = (pn < NPAIRS);

        // stage current pair's displacements into smem
        if (g) {
            PairDisp* e = &sd[warp][lane];
            *(u64*)&e->x[0] = packf2(pax - qax, pbx - qbx);
            *(u64*)&e->y[0] = packf2(pay - qay, pby - qby);
            *(u64*)&e->z[0] = packf2(paz - qaz, pbz - qbz);
        }

        // prefetch NEXT pair's verts (idx already in regs, loaded a full loop ago)
        float npax=0,npay=0,npaz=0, npbx=0,npby=0,npbz=0;
        float nqax=0,nqay=0,nqaz=0, nqbx=0,nqby=0,nqbz=0;
        if (g && more) {
            const int nvb = (pn >> 12) * (V_ * 3);
            const float* pa = verts + nvb + nidxA * 3;
            const float* pb = verts + nvb + nidxB * 3;
            npax = pa[0]; npay = pa[1]; npaz = pa[2];
            npbx = pb[0]; npby = pb[1]; npbz = pb[2];
            const float* qa = verts + (2*pn)     * 3;
            const float* qb = verts + (2*pn + 1) * 3;
            nqax = qa[0]; nqay = qa[1]; nqaz = qa[2];
            nqbx = qb[0]; nqby = qb[1]; nqbz = qb[2];
        }
        // prefetch idx TWO pairs ahead
        int nnidxA = 0, nnidxB = 0;
        {
            int pnn = pn + NWARPS_;
            if (g && pnn < NPAIRS) {
                nnidxA = nb[(2*pnn)     * N_ + lane];
                nnidxB = nb[(2*pnn + 1) * N_ + lane];
            }
        }

        __syncwarp();

        // compute: relu(max_n theta) via max seeded at 0; rows packed in f32x2
        float m0a=0.f,m1a=0.f,m2a=0.f,m3a=0.f;
        float m0b=0.f,m1b=0.f,m2b=0.f,m3b=0.f;
        #pragma unroll
        for (int j = 0; j < N_; j++) {
            const u64 x2 = *(const u64*)&sd[warp][j].x[0];
            const u64 y2 = *(const u64*)&sd[warp][j].y[0];
            const u64 z2 = *(const u64*)&sd[warp][j].z[0];

            u64 t0, t1, t2, t3;
            MUL_F32X2_(t0, z2, D2[0]); FMA_F32X2(t0, y2, D1[0], t0); FMA_F32X2(t0, x2, D0[0], t0);
            MUL_F32X2_(t1, z2, D2[1]); FMA_F32X2(t1, y2, D1[1], t1); FMA_F32X2(t1, x2, D0[1], t1);
            MUL_F32X2_(t2, z2, D2[2]); FMA_F32X2(t2, y2, D1[2], t2); FMA_F32X2(t2, x2, D0[2], t2);
            MUL_F32X2_(t3, z2, D2[3]); FMA_F32X2(t3, y2, D1[3], t3); FMA_F32X2(t3, x2, D0[3], t3);

            float a, b;
            unpackf2(a, b, t0); m0a = fmaxf(m0a, a); m0b = fmaxf(m0b, b);
            unpackf2(a, b, t1); m1a = fmaxf(m1a, a); m1b = fmaxf(m1b, b);
            unpackf2(a, b, t2); m2a = fmaxf(m2a, a); m2b = fmaxf(m2b, b);
            unpackf2(a, b, t3); m3a = fmaxf(m3a, a); m3b = fmaxf(m3b, b);
        }

        out[rA * K_ + lane] = fmaf(m0a, w0, fmaf(m1a, w1, fmaf(m2a, w2, m3a * w3)));
        out[rB * K_ + lane] = fmaf(m0b, w0, fmaf(m1b, w1, fmaf(m2b, w2, m3b * w3)));

        if (!more) break;

        __syncwarp();   // protect smem before next chunk's STS

        // rotate pipeline registers
        p = pn;
        pax=npax; pay=npay; paz=npaz; pbx=npbx; pby=npby; pbz=npbz;
        qax=nqax; qay=nqay; qaz=nqaz; qbx=nqbx; qby=nqby; qbz=nqbz;
        nidxA = nnidxA; nidxB = nnidxB;
    }
}

extern "C" void kernel_launch(void* const* d_in, const int* in_sizes, int n_in,
                              void* d_out, int out_size)
{
    const int*   nb      = (const int*)  d_in[0];
    const float* verts   = (const float*)d_in[1];
    const float* weights = (const float*)d_in[2];
    const float* disp    = (const float*)d_in[3];
    float*       out     = (float*)      d_out;

    op3d_kernel<<<BLOCKS_, THREADS_>>>(nb, verts, weights, disp, out);
}

// round 4
// speedup vs baseline: 1.5150x; 1.5150x over previous
#include <cuda_runtime.h>

// Operator3D: bs=4, v=8192, n=20, SUPPORT=4, KERNEL=32  (S*K = 128)
// inputs: [0] neighbor_index int32 (bs,v,n)
//         [1] vertices       f32   (bs,v,3)
//         [2] weights        f32   (1,1,4,32)
//         [3] displacement   f32   (3,128)
// output: feature f32 (bs,v,32)
//
// One warp per row (lane = kernel channel k), grid-stride over rows.
// Grid sized to exactly 7 blocks/SM * 148 SMs so occupancy is ~56/64 warps:
// the per-row dependent gather chain (LDG idx -> LDG verts) is covered by
// warp-level parallelism instead of software pipelining (which cost too many
// registers in R3).

#define BS_   4
#define V_    8192
#define N_    20
#define K_    32
#define SK_   128
#define ROWS_ (BS_ * V_)

#define WPB      8
#define THREADS_ (WPB * 32)
#define BLOCKS_  1036                 // 7 * 148: full residency, one wave
#define NWARPS_  (BLOCKS_ * WPB)      // 8288 -> ~3.95 rows/warp

__global__ __launch_bounds__(THREADS_)
void op3d_kernel(const int*   __restrict__ nb,
                 const float* __restrict__ verts,
                 const float* __restrict__ weights,
                 const float* __restrict__ disp,
                 float*       __restrict__ out)
{
    __shared__ float4 sdisp[WPB][N_];

    const int warp  = threadIdx.x >> 5;
    const int lane  = threadIdx.x & 31;
    const int gwarp = blockIdx.x * WPB + warp;

    // Per-lane constants: displacement columns for k = s*32 + lane, s=0..3,
    // rows d=0..2 of the (3,128) displacement matrix; plus weights.
    const float d00 = disp[0 * SK_ +  0 + lane];
    const float d01 = disp[0 * SK_ + 32 + lane];
    const float d02 = disp[0 * SK_ + 64 + lane];
    const float d03 = disp[0 * SK_ + 96 + lane];
    const float d10 = disp[1 * SK_ +  0 + lane];
    const float d11 = disp[1 * SK_ + 32 + lane];
    const float d12 = disp[1 * SK_ + 64 + lane];
    const float d13 = disp[1 * SK_ + 96 + lane];
    const float d20 = disp[2 * SK_ +  0 + lane];
    const float d21 = disp[2 * SK_ + 32 + lane];
    const float d22 = disp[2 * SK_ + 64 + lane];
    const float d23 = disp[2 * SK_ + 96 + lane];
    const float w0  = weights[ 0 + lane];
    const float w1  = weights[32 + lane];
    const float w2  = weights[64 + lane];
    const float w3  = weights[96 + lane];

    for (int r = gwarp; r < ROWS_; r += NWARPS_) {
        const int b     = r >> 13;            // r / V_  (V_ = 8192)
        const int vbase = b * (V_ * 3);

        if (lane < N_) {
            const int idx = nb[r * N_ + lane];
            const float* p = verts + vbase + idx * 3;
            const float* q = verts + r * 3;           // broadcast line (L1 hit)
            float dx = p[0] - q[0];
            float dy = p[1] - q[1];
            float dz = p[2] - q[2];
            sdisp[warp][lane] = make_float4(dx, dy, dz, 0.0f);
        }
        __syncwarp();

        // running max seeded at 0 == relu(max_n theta) since relu is monotone
        float m0 = 0.0f, m1 = 0.0f, m2 = 0.0f, m3 = 0.0f;
        #pragma unroll
        for (int j = 0; j < N_; j++) {
            const float4 d = sdisp[warp][j];
            float t0 = fmaf(d.x, d00, fmaf(d.y, d10, d.z * d20));
            float t1 = fmaf(d.x, d01, fmaf(d.y, d11, d.z * d21));
            float t2 = fmaf(d.x, d02, fmaf(d.y, d12, d.z * d22));
            float t3 = fmaf(d.x, d03, fmaf(d.y, d13, d.z * d23));
            m0 = fmaxf(m0, t0);
            m1 = fmaxf(m1, t1);
            m2 = fmaxf(m2, t2);
            m3 = fmaxf(m3, t3);
        }

        out[r * K_ + lane] = fmaf(m0, w0, fmaf(m1, w1, fmaf(m2, w2, m3 * w3)));
        __syncwarp();   // protect smem before next iteration's writes
    }
}

extern "C" void kernel_launch(void* const* d_in, const int* in_sizes, int n_in,
                              void* d_out, int out_size)
{
    const int*   nb      = (const int*)  d_in[0];
    const float* verts   = (const float*)d_in[1];
    const float* weights = (const float*)d_in[2];
    const float* disp    = (const float*)d_in[3];
    float*       out     = (float*)      d_out;

    op3d_kernel<<<BLOCKS_, THREADS_>>>(nb, verts, weights, disp, out);
}